// round 6
// baseline (speedup 1.0000x reference)
#include <cuda_runtime.h>
#include <cstdint>

#define D 256
#define NWARPS 8
#define GPI 8                   // groups per block-iteration (one per warp)
#define TILE_F4 1024            // per tensor tile: 16 rows x 64 float4 = 16 KB
#define BUF_F4 2048             // zjs tile + zis tile = 32 KB
#define SMEM_BYTES (2 * BUF_F4 * 16)   // double-buffered: 64 KB
#define GRID 444                // 3 blocks/SM * 148 SMs (smem-bound residency)

__device__ float        g_partials[1024];
__device__ unsigned int g_ticket = 0;   // reset by last block -> graph-replayable

__device__ __forceinline__ float dot4(float4 a, float4 b) {
    return fmaf(a.x, b.x, fmaf(a.y, b.y, fmaf(a.z, b.z, a.w * b.w)));
}

__device__ __forceinline__ void butterfly10(float v[10]) {
    #pragma unroll
    for (int off = 16; off > 0; off >>= 1) {
        #pragma unroll
        for (int k = 0; k < 10; k++)
            v[k] += __shfl_xor_sync(0xFFFFFFFFu, v[k], off);
    }
}

// Lanes 0..3 each evaluate one anchor's weighted 3-way log-softmax; others 0.
__device__ __forceinline__ float softmax_acc(const float v[10], int lane,
                                             const float* __restrict__ sl) {
    if (lane >= 4) return 0.0f;

    float r0 = rsqrtf(fmaxf(v[0], 1e-16f));
    float r1 = rsqrtf(fmaxf(v[1], 1e-16f));
    float r2 = rsqrtf(fmaxf(v[2], 1e-16f));
    float r3 = rsqrtf(fmaxf(v[3], 1e-16f));

    float s01 = v[4] * (r0 * r1);
    float s02 = v[5] * (r0 * r2);
    float s03 = v[6] * (r0 * r3);
    float s12 = v[7] * (r1 * r2);
    float s13 = v[8] * (r1 * r3);
    float s23 = v[9] * (r2 * r3);

    // anchor i logits (pos, neg0, neg1):
    // i=0:(s02,s01,s03) i=1:(s13,s01,s12) i=2:(s02,s12,s23) i=3:(s13,s03,s23)
    float p  = (lane & 1)  ? s13 : s02;
    float n0 = (lane < 2)  ? s01 : ((lane == 2) ? s12 : s03);
    float n1 = (lane == 0) ? s03 : ((lane == 1) ? s12 : s23);

    const float invT = 2.0f;  // 1/TEMPERATURE, T = 0.5
    float l0 = p * invT, l1 = n0 * invT, l2 = n1 * invT;

    float m   = fmaxf(l0, fmaxf(l1, l2));
    float e   = __expf(l0 - m) + __expf(l1 - m) + __expf(l2 - m);
    float lse = m + __logf(e);

    float w0 = __ldg(sl + lane * 3 + 0);
    float w1 = __ldg(sl + lane * 3 + 1);
    float w2 = __ldg(sl + lane * 3 + 2);

    return (lse - l0) * w0 + (lse - l1) * w1 + (lse - l2) * w2;
}

__device__ __forceinline__ void cp16(uint32_t dst, const void* src, int pred) {
    asm volatile(
        "{\n\t.reg .pred p;\n\tsetp.ne.s32 p, %2, 0;\n\t"
        "@p cp.async.cg.shared.global [%0], [%1], 16;\n\t}\n"
        :: "r"(dst), "l"(src), "r"(pred));
}

__global__ __launch_bounds__(256)
void ntxent_kernel(const float* __restrict__ zis,
                   const float* __restrict__ zjs,
                   const float* __restrict__ soft_labels,
                   float* __restrict__ out,
                   int nc, int nf4, int niter)
{
    extern __shared__ float4 sbuf[];   // [2][BUF_F4]
    __shared__ float wsum[NWARPS];
    __shared__ bool  is_last;

    const int tid  = threadIdx.x;
    const int warp = tid >> 5;
    const int lane = tid & 31;

    uint32_t sbase;
    asm("{ .reg .u64 t; cvta.to.shared.u64 t, %1; cvt.u32.u64 %0, t; }"
        : "=r"(sbase) : "l"(sbuf));

    const float4* zj4 = reinterpret_cast<const float4*>(zjs);
    const float4* zi4 = reinterpret_cast<const float4*>(zis);

    // Prefetch tile `it` (16 rows of zjs + 16 rows of zis, both contiguous)
    // into buffer `bufsel`. 256 threads x 16B x 8 = 32 KB.
    auto prefetch = [&](int it, int bufsel) {
        int base = it * TILE_F4;
        uint32_t dst = sbase + (uint32_t)bufsel * (BUF_F4 * 16);
        #pragma unroll
        for (int p = 0; p < 4; p++) {
            int idx = base + p * 256 + tid;
            cp16(dst + (uint32_t)(p * 256 + tid) * 16, zj4 + idx, idx < nf4);
        }
        #pragma unroll
        for (int p = 0; p < 4; p++) {
            int idx = base + p * 256 + tid;
            cp16(dst + (uint32_t)(TILE_F4 + p * 256 + tid) * 16, zi4 + idx, idx < nf4);
        }
    };

    float acc = 0.0f;
    int it  = blockIdx.x;
    int buf = 0;

    if (it < niter) prefetch(it, 0);
    asm volatile("cp.async.commit_group;");

    for (; it < niter; it += gridDim.x, buf ^= 1) {
        int itn = it + gridDim.x;
        if (itn < niter) prefetch(itn, buf ^ 1);
        asm volatile("cp.async.commit_group;");
        asm volatile("cp.async.wait_group 1;");   // current tile resident
        __syncthreads();

        int g = it * GPI + warp;
        if (g < nc) {
            const float4* sj = sbuf + (size_t)buf * BUF_F4 + warp * 128;
            const float4* si = sj + TILE_F4;
            // 8 x LDS.128, conflict-free
            float4 a0 = sj[lane];      float4 a1 = sj[lane + 32];
            float4 b0 = sj[lane + 64]; float4 b1 = sj[lane + 96];
            float4 c0 = si[lane];      float4 c1 = si[lane + 32];
            float4 d0 = si[lane + 64]; float4 d1 = si[lane + 96];

            float v[10];
            v[0] = dot4(a0, a0) + dot4(a1, a1);
            v[1] = dot4(b0, b0) + dot4(b1, b1);
            v[2] = dot4(c0, c0) + dot4(c1, c1);
            v[3] = dot4(d0, d0) + dot4(d1, d1);
            v[4] = dot4(a0, b0) + dot4(a1, b1);
            v[5] = dot4(a0, c0) + dot4(a1, c1);
            v[6] = dot4(a0, d0) + dot4(a1, d1);
            v[7] = dot4(b0, c0) + dot4(b1, c1);
            v[8] = dot4(b0, d0) + dot4(b1, d1);
            v[9] = dot4(c0, d0) + dot4(c1, d1);

            butterfly10(v);
            acc += softmax_acc(v, lane, soft_labels);
        }
        __syncthreads();   // compute done before this buffer is refilled
    }

    // fold lanes 0..3 -> lane 0
    acc += __shfl_xor_sync(0xFFFFFFFFu, acc, 1);
    acc += __shfl_xor_sync(0xFFFFFFFFu, acc, 2);
    if (lane == 0) wsum[warp] = acc;
    __syncthreads();

    if (tid == 0) {
        float t = 0.0f;
        #pragma unroll
        for (int w = 0; w < NWARPS; w++) t += wsum[w];
        g_partials[blockIdx.x] = t;
        __threadfence();
        unsigned old = atomicAdd(&g_ticket, 1u);
        is_last = (old == (unsigned)(gridDim.x - 1));
    }
    __syncthreads();

    if (is_last) {
        __threadfence();
        float t = 0.0f;
        for (int i = tid; i < (int)gridDim.x; i += 256)
            t += g_partials[i];
        #pragma unroll
        for (int off = 16; off > 0; off >>= 1)
            t += __shfl_xor_sync(0xFFFFFFFFu, t, off);
        if (lane == 0) wsum[warp] = t;
        __syncthreads();
        if (tid == 0) {
            float tot = 0.0f;
            #pragma unroll
            for (int w = 0; w < NWARPS; w++) tot += wsum[w];
            out[0] = tot * (1.0f / (4.0f * (float)nc));  // 1/(2n)
            g_ticket = 0;   // reset for graph replay
        }
    }
}

extern "C" void kernel_launch(void* const* d_in, const int* in_sizes, int n_in,
                              void* d_out, int out_size)
{
    const float* zis = (const float*)d_in[0];
    const float* zjs = (const float*)d_in[1];
    const float* sl  = (const float*)d_in[2];
    float* out = (float*)d_out;

    int n     = in_sizes[0] / D;   // 65536 rows
    int nc    = n / 2;             // 32768 groups
    int nf4   = in_sizes[0] / 4;   // float4 count per tensor
    int niter = (nc + GPI - 1) / GPI;

    static bool attr_set = false;
    if (!attr_set) {
        cudaFuncSetAttribute(ntxent_kernel,
                             cudaFuncAttributeMaxDynamicSharedMemorySize,
                             SMEM_BYTES);
        attr_set = true;
    }

    ntxent_kernel<<<GRID, 256, SMEM_BYTES>>>(zis, zjs, sl, out, nc, nf4, niter);
}

// round 7
// speedup vs baseline: 1.0067x; 1.0067x over previous
#include <cuda_runtime.h>
#include <cstdint>

#define D 256
#define NWARPS 8
#define NTHREADS (NWARPS * 32)
#define GRID 444                 // 3 blocks/SM * 148 SMs
#define TILE_BYTES 4096          // one group: 4 rows x 1 KB
#define WARP_SMEM (2 * TILE_BYTES)          // double buffer per warp
#define SMEM_BYTES (NWARPS * WARP_SMEM)     // 64 KB dynamic

__device__ float        g_partials[1024];
__device__ unsigned int g_ticket = 0;   // reset by last block -> graph-replayable

__device__ __forceinline__ float dot4(float4 a, float4 b) {
    return fmaf(a.x, b.x, fmaf(a.y, b.y, fmaf(a.z, b.z, a.w * b.w)));
}

__device__ __forceinline__ void butterfly10(float v[10]) {
    #pragma unroll
    for (int off = 16; off > 0; off >>= 1) {
        #pragma unroll
        for (int k = 0; k < 10; k++)
            v[k] += __shfl_xor_sync(0xFFFFFFFFu, v[k], off);
    }
}

// Lanes 0..3 each evaluate one anchor's weighted 3-way log-softmax; others 0.
__device__ __forceinline__ float softmax_acc(const float v[10], int lane,
                                             const float* __restrict__ sl) {
    if (lane >= 4) return 0.0f;

    float r0 = rsqrtf(fmaxf(v[0], 1e-16f));
    float r1 = rsqrtf(fmaxf(v[1], 1e-16f));
    float r2 = rsqrtf(fmaxf(v[2], 1e-16f));
    float r3 = rsqrtf(fmaxf(v[3], 1e-16f));

    float s01 = v[4] * (r0 * r1);
    float s02 = v[5] * (r0 * r2);
    float s03 = v[6] * (r0 * r3);
    float s12 = v[7] * (r1 * r2);
    float s13 = v[8] * (r1 * r3);
    float s23 = v[9] * (r2 * r3);

    // anchor i logits (pos, neg0, neg1):
    // i=0:(s02,s01,s03) i=1:(s13,s01,s12) i=2:(s02,s12,s23) i=3:(s13,s03,s23)
    float p  = (lane & 1)  ? s13 : s02;
    float n0 = (lane < 2)  ? s01 : ((lane == 2) ? s12 : s03);
    float n1 = (lane == 0) ? s03 : ((lane == 1) ? s12 : s23);

    const float invT = 2.0f;  // 1/TEMPERATURE, T = 0.5
    float l0 = p * invT, l1 = n0 * invT, l2 = n1 * invT;

    float m   = fmaxf(l0, fmaxf(l1, l2));
    float e   = __expf(l0 - m) + __expf(l1 - m) + __expf(l2 - m);
    float lse = m + __logf(e);

    float w0 = __ldg(sl + lane * 3 + 0);
    float w1 = __ldg(sl + lane * 3 + 1);
    float w2 = __ldg(sl + lane * 3 + 2);

    return (lse - l0) * w0 + (lse - l1) * w1 + (lse - l2) * w2;
}

__device__ __forceinline__ void cp16(uint32_t dst, const void* src) {
    asm volatile("cp.async.cg.shared.global [%0], [%1], 16;"
                 :: "r"(dst), "l"(src));
}
__device__ __forceinline__ void cp_commit() {
    asm volatile("cp.async.commit_group;" ::: "memory");
}
__device__ __forceinline__ void cp_wait1() {
    asm volatile("cp.async.wait_group 1;" ::: "memory");
}

__global__ __launch_bounds__(NTHREADS)
void ntxent_kernel(const float* __restrict__ zis,
                   const float* __restrict__ zjs,
                   const float* __restrict__ soft_labels,
                   float* __restrict__ out,
                   int nc, int niter)
{
    extern __shared__ float4 sbuf[];
    __shared__ float wsum[NWARPS];
    __shared__ bool  is_last;

    const int tid  = threadIdx.x;
    const int warp = tid >> 5;
    const int lane = tid & 31;

    const int W  = gridDim.x * NWARPS;            // total warps in grid
    const int w0 = blockIdx.x * NWARPS + warp;    // this warp's id

    uint32_t wbase;   // smem byte address of this warp's 8 KB region
    asm("{ .reg .u64 t; cvta.to.shared.u64 t, %1; cvt.u32.u64 %0, t; }"
        : "=r"(wbase) : "l"(sbuf));
    wbase += (uint32_t)warp * WARP_SMEM;

    const float4* zj4 = reinterpret_cast<const float4*>(zjs);
    const float4* zi4 = reinterpret_cast<const float4*>(zis);

    // Issue one group's 4 KB into buffer `b` (8 x 16B cp.async per lane).
    // zjs pair block: f4[g*128 .. g*128+127]; same for zis. smem layout:
    // [0:128) f4 = zjs pair, [128:256) f4 = zis pair.
    auto issue_tile = [&](int g, int b) {
        if (g < nc) {
            uint32_t dst = wbase + (uint32_t)b * TILE_BYTES;
            const float4* sj = zj4 + (size_t)g * 128;
            const float4* si = zi4 + (size_t)g * 128;
            #pragma unroll
            for (int p = 0; p < 4; p++)
                cp16(dst + (uint32_t)(lane + 32 * p) * 16, sj + lane + 32 * p);
            #pragma unroll
            for (int p = 0; p < 4; p++)
                cp16(dst + (uint32_t)(128 + lane + 32 * p) * 16, si + lane + 32 * p);
        }
        cp_commit();   // always commit to keep group counting balanced
    };

    float acc = 0.0f;

    // Prologue: fill both buffers
    issue_tile(w0,     0);
    issue_tile(w0 + W, 1);

    // Per-warp independent pipeline — NO block barriers in the loop.
    for (int t = 0; t < niter; t++) {
        cp_wait1();               // tile t resident (<=1 group still pending)

        const int g = w0 + t * W;
        float4 a0, a1, b0, b1, c0, c1, d0, d1;
        if (g < nc) {
            const float4* sj = sbuf + ((size_t)warp * 2 + (t & 1)) * 256;
            const float4* si = sj + 128;
            a0 = sj[lane];      a1 = sj[lane + 32];
            b0 = sj[lane + 64]; b1 = sj[lane + 96];
            c0 = si[lane];      c1 = si[lane + 32];
            d0 = si[lane + 64]; d1 = si[lane + 96];
        }

        // Refill this buffer for tile t+2 (lands ~600+ cyc later, far after
        // the LDS above complete; same thread covers same bytes).
        issue_tile(w0 + (t + 2) * W, t & 1);

        if (g < nc) {
            float v[10];
            v[0] = dot4(a0, a0) + dot4(a1, a1);
            v[1] = dot4(b0, b0) + dot4(b1, b1);
            v[2] = dot4(c0, c0) + dot4(c1, c1);
            v[3] = dot4(d0, d0) + dot4(d1, d1);
            v[4] = dot4(a0, b0) + dot4(a1, b1);
            v[5] = dot4(a0, c0) + dot4(a1, c1);
            v[6] = dot4(a0, d0) + dot4(a1, d1);
            v[7] = dot4(b0, c0) + dot4(b1, c1);
            v[8] = dot4(b0, d0) + dot4(b1, d1);
            v[9] = dot4(c0, d0) + dot4(c1, d1);

            butterfly10(v);
            acc += softmax_acc(v, lane, soft_labels);
        }
    }
    asm volatile("cp.async.wait_group 0;" ::: "memory");

    // fold lanes 0..3 -> lane 0
    acc += __shfl_xor_sync(0xFFFFFFFFu, acc, 1);
    acc += __shfl_xor_sync(0xFFFFFFFFu, acc, 2);
    if (lane == 0) wsum[warp] = acc;
    __syncthreads();

    if (tid == 0) {
        float t = 0.0f;
        #pragma unroll
        for (int w = 0; w < NWARPS; w++) t += wsum[w];
        g_partials[blockIdx.x] = t;
        __threadfence();
        unsigned old = atomicAdd(&g_ticket, 1u);
        is_last = (old == (unsigned)(gridDim.x - 1));
    }
    __syncthreads();

    if (is_last) {
        __threadfence();
        float t = 0.0f;
        for (int i = tid; i < (int)gridDim.x; i += NTHREADS)
            t += g_partials[i];
        #pragma unroll
        for (int off = 16; off > 0; off >>= 1)
            t += __shfl_xor_sync(0xFFFFFFFFu, t, off);
        if (lane == 0) wsum[warp] = t;
        __syncthreads();
        if (tid == 0) {
            float tot = 0.0f;
            #pragma unroll
            for (int w = 0; w < NWARPS; w++) tot += wsum[w];
            out[0] = tot * (1.0f / (4.0f * (float)nc));  // 1/(2n)
            g_ticket = 0;   // reset for graph replay
        }
    }
}

extern "C" void kernel_launch(void* const* d_in, const int* in_sizes, int n_in,
                              void* d_out, int out_size)
{
    const float* zis = (const float*)d_in[0];
    const float* zjs = (const float*)d_in[1];
    const float* sl  = (const float*)d_in[2];
    float* out = (float*)d_out;

    int n  = in_sizes[0] / D;   // 65536 rows
    int nc = n / 2;             // 32768 groups

    int W     = GRID * NWARPS;            // 3552 warps
    int niter = (nc + W - 1) / W;         // 10

    static bool attr_set = false;
    if (!attr_set) {
        cudaFuncSetAttribute(ntxent_kernel,
                             cudaFuncAttributeMaxDynamicSharedMemorySize,
                             SMEM_BYTES);
        attr_set = true;
    }

    ntxent_kernel<<<GRID, NTHREADS, SMEM_BYTES>>>(zis, zjs, sl, out, nc, niter);
}

// round 8
// speedup vs baseline: 1.1380x; 1.1304x over previous
#include <cuda_runtime.h>
#include <cstdint>

#define D 256
#define NWARPS 16
#define NTHREADS 512
#define GRID 148                  // persistent: 1 block per SM
#define NSTAGES 3
#define GROUPS_PER_TILE 16        // 16 groups/stage, one per warp
#define TILE_HALF 32768           // bytes per tensor per stage (32 rows x 1KB)
#define STAGE_BYTES (2 * TILE_HALF)
#define SMEM_BYTES (NSTAGES * STAGE_BYTES)   // 192 KB
#define STAGE_F4 (STAGE_BYTES / 16)          // 4096 float4 per stage

__device__ float        g_partials[GRID];
__device__ unsigned int g_ticket = 0;   // reset by last block -> graph-replayable

__device__ __forceinline__ float dot4(float4 a, float4 b) {
    return fmaf(a.x, b.x, fmaf(a.y, b.y, fmaf(a.z, b.z, a.w * b.w)));
}

__device__ __forceinline__ void butterfly10(float v[10]) {
    #pragma unroll
    for (int off = 16; off > 0; off >>= 1) {
        #pragma unroll
        for (int k = 0; k < 10; k++)
            v[k] += __shfl_xor_sync(0xFFFFFFFFu, v[k], off);
    }
}

// Lanes 0..3 each evaluate one anchor's weighted 3-way log-softmax; others 0.
__device__ __forceinline__ float softmax_acc(const float v[10], int lane,
                                             const float* __restrict__ sl) {
    if (lane >= 4) return 0.0f;

    float r0 = rsqrtf(fmaxf(v[0], 1e-16f));
    float r1 = rsqrtf(fmaxf(v[1], 1e-16f));
    float r2 = rsqrtf(fmaxf(v[2], 1e-16f));
    float r3 = rsqrtf(fmaxf(v[3], 1e-16f));

    float s01 = v[4] * (r0 * r1);
    float s02 = v[5] * (r0 * r2);
    float s03 = v[6] * (r0 * r3);
    float s12 = v[7] * (r1 * r2);
    float s13 = v[8] * (r1 * r3);
    float s23 = v[9] * (r2 * r3);

    // anchor i logits (pos, neg0, neg1):
    // i=0:(s02,s01,s03) i=1:(s13,s01,s12) i=2:(s02,s12,s23) i=3:(s13,s03,s23)
    float p  = (lane & 1)  ? s13 : s02;
    float n0 = (lane < 2)  ? s01 : ((lane == 2) ? s12 : s03);
    float n1 = (lane == 0) ? s03 : ((lane == 1) ? s12 : s23);

    const float invT = 2.0f;  // 1/TEMPERATURE, T = 0.5
    float l0 = p * invT, l1 = n0 * invT, l2 = n1 * invT;

    float m   = fmaxf(l0, fmaxf(l1, l2));
    float e   = __expf(l0 - m) + __expf(l1 - m) + __expf(l2 - m);
    float lse = m + __logf(e);

    float w0 = __ldg(sl + lane * 3 + 0);
    float w1 = __ldg(sl + lane * 3 + 1);
    float w2 = __ldg(sl + lane * 3 + 2);

    return (lse - l0) * w0 + (lse - l1) * w1 + (lse - l2) * w2;
}

__device__ __forceinline__ uint32_t smem_u32(const void* p) {
    uint32_t a;
    asm("{ .reg .u64 t; cvta.to.shared.u64 t, %1; cvt.u32.u64 %0, t; }"
        : "=r"(a) : "l"(p));
    return a;
}

__device__ __forceinline__ void mbar_init(uint32_t mbar, uint32_t cnt) {
    asm volatile("mbarrier.init.shared.b64 [%0], %1;" :: "r"(mbar), "r"(cnt) : "memory");
}
__device__ __forceinline__ void mbar_expect_tx(uint32_t mbar, uint32_t bytes) {
    asm volatile("mbarrier.arrive.expect_tx.shared.b64 _, [%0], %1;"
                 :: "r"(mbar), "r"(bytes) : "memory");
}
__device__ __forceinline__ void mbar_arrive(uint32_t mbar) {
    asm volatile("mbarrier.arrive.shared.b64 _, [%0];" :: "r"(mbar) : "memory");
}
__device__ __forceinline__ void mbar_wait(uint32_t mbar, uint32_t parity) {
    asm volatile(
        "{\n\t"
        ".reg .pred P;\n\t"
        "W_%=:\n\t"
        "mbarrier.try_wait.parity.acquire.cta.shared::cta.b64 P, [%0], %1, 0x989680;\n\t"
        "@P bra D_%=;\n\t"
        "bra W_%=;\n\t"
        "D_%=:\n\t"
        "}"
        :: "r"(mbar), "r"(parity) : "memory");
}
// One instruction moves TILE_HALF bytes; completion signals the mbarrier.
__device__ __forceinline__ void bulk_g2s(uint32_t dst, const void* src,
                                         uint32_t bytes, uint32_t mbar) {
    asm volatile(
        "cp.async.bulk.shared::cta.global.mbarrier::complete_tx::bytes [%0], [%1], %2, [%3];"
        :: "r"(dst), "l"(src), "r"(bytes), "r"(mbar) : "memory");
}

__global__ __launch_bounds__(NTHREADS, 1)
void ntxent_kernel(const float* __restrict__ zis,
                   const float* __restrict__ zjs,
                   const float* __restrict__ soft_labels,
                   float* __restrict__ out,
                   int nc, int ntiles, int niter)
{
    extern __shared__ float4 sbuf[];
    __shared__ __align__(8) uint64_t mbar_full_s[NSTAGES];
    __shared__ float wsum[NWARPS];
    __shared__ bool  is_last;

    const int tid  = threadIdx.x;
    const int warp = tid >> 5;
    const int lane = tid & 31;

    const uint32_t sb   = smem_u32(sbuf);
    const uint32_t mb0  = smem_u32(mbar_full_s);

    if (tid == 0) {
        #pragma unroll
        for (int s = 0; s < NSTAGES; s++) mbar_init(mb0 + s * 8, 1);
    }
    __syncthreads();

    const char* zjb = reinterpret_cast<const char*>(zjs);
    const char* zib = reinterpret_cast<const char*>(zis);

    // Issue tile for logical step t into stage t % NSTAGES (tid 0 only).
    auto issue = [&](int t) {
        int s    = t % NSTAGES;
        int tile = blockIdx.x + t * GRID;
        uint32_t mb = mb0 + s * 8;
        if (tile < ntiles) {
            mbar_expect_tx(mb, STAGE_BYTES);
            uint32_t dst = sb + (uint32_t)s * STAGE_BYTES;
            bulk_g2s(dst,             zjb + (size_t)tile * TILE_HALF, TILE_HALF, mb);
            bulk_g2s(dst + TILE_HALF, zib + (size_t)tile * TILE_HALF, TILE_HALF, mb);
        } else {
            mbar_arrive(mb);   // dummy flip so waits stay balanced
        }
    };

    if (tid == 0) {
        issue(0); issue(1); issue(2);
    }

    float acc = 0.0f;

    for (int t = 0; t < niter; t++) {
        const int s = t % NSTAGES;
        mbar_wait(mb0 + s * 8, (uint32_t)((t / NSTAGES) & 1));

        const int tile = blockIdx.x + t * GRID;
        const int g    = tile * GROUPS_PER_TILE + warp;
        if (tile < ntiles && g < nc) {
            // stage layout: [0:2048) f4 = 32 zjs rows, [2048:4096) f4 = 32 zis rows
            const float4* sj = sbuf + (size_t)s * STAGE_F4 + warp * 128;
            const float4* si = sj + 2048;

            float4 a0 = sj[lane];      float4 a1 = sj[lane + 32];
            float4 b0 = sj[lane + 64]; float4 b1 = sj[lane + 96];
            float4 c0 = si[lane];      float4 c1 = si[lane + 32];
            float4 d0 = si[lane + 64]; float4 d1 = si[lane + 96];

            float v[10];
            v[0] = dot4(a0, a0) + dot4(a1, a1);
            v[1] = dot4(b0, b0) + dot4(b1, b1);
            v[2] = dot4(c0, c0) + dot4(c1, c1);
            v[3] = dot4(d0, d0) + dot4(d1, d1);
            v[4] = dot4(a0, b0) + dot4(a1, b1);
            v[5] = dot4(a0, c0) + dot4(a1, c1);
            v[6] = dot4(a0, d0) + dot4(a1, d1);
            v[7] = dot4(b0, c0) + dot4(b1, c1);
            v[8] = dot4(b0, d0) + dot4(b1, d1);
            v[9] = dot4(c0, d0) + dot4(c1, d1);

            butterfly10(v);
            acc += softmax_acc(v, lane, soft_labels);
        }

        __syncthreads();             // whole block done with stage s
        if (tid == 0) issue(t + NSTAGES);
    }

    // fold lanes 0..3 -> lane 0
    acc += __shfl_xor_sync(0xFFFFFFFFu, acc, 1);
    acc += __shfl_xor_sync(0xFFFFFFFFu, acc, 2);
    if (lane == 0) wsum[warp] = acc;
    __syncthreads();

    if (tid == 0) {
        float t = 0.0f;
        #pragma unroll
        for (int w = 0; w < NWARPS; w++) t += wsum[w];
        g_partials[blockIdx.x] = t;
        __threadfence();
        unsigned old = atomicAdd(&g_ticket, 1u);
        is_last = (old == (unsigned)(gridDim.x - 1));
    }
    __syncthreads();

    if (is_last) {
        __threadfence();
        float t = 0.0f;
        for (int i = tid; i < (int)gridDim.x; i += NTHREADS)
            t += g_partials[i];
        #pragma unroll
        for (int off = 16; off > 0; off >>= 1)
            t += __shfl_xor_sync(0xFFFFFFFFu, t, off);
        if (lane == 0) wsum[warp] = t;
        __syncthreads();
        if (tid == 0) {
            float tot = 0.0f;
            #pragma unroll
            for (int w = 0; w < NWARPS; w++) tot += wsum[w];
            out[0] = tot * (1.0f / (4.0f * (float)nc));  // 1/(2n)
            g_ticket = 0;   // reset for graph replay
        }
    }
}

extern "C" void kernel_launch(void* const* d_in, const int* in_sizes, int n_in,
                              void* d_out, int out_size)
{
    const float* zis = (const float*)d_in[0];
    const float* zjs = (const float*)d_in[1];
    const float* sl  = (const float*)d_in[2];
    float* out = (float*)d_out;

    int n      = in_sizes[0] / D;                 // 65536 rows
    int nc     = n / 2;                            // 32768 groups
    int ntiles = (nc + GROUPS_PER_TILE - 1) / GROUPS_PER_TILE;   // 2048
    int niter  = (ntiles + GRID - 1) / GRID;       // 14

    static bool attr_set = false;
    if (!attr_set) {
        cudaFuncSetAttribute(ntxent_kernel,
                             cudaFuncAttributeMaxDynamicSharedMemorySize,
                             SMEM_BYTES);
        attr_set = true;
    }

    ntxent_kernel<<<GRID, NTHREADS, SMEM_BYTES>>>(zis, zjs, sl, out,
                                                  nc, ntiles, niter);
}

// round 9
// speedup vs baseline: 1.1493x; 1.0099x over previous
#include <cuda_runtime.h>

#define NWARPS 8
#define NTHREADS 256
#define GRID 740                 // persistent: 5 blocks/SM * 148 SMs
#define D 256
#define F4_PER_ROW (D/4)

__device__ float        g_partials[1024];
__device__ unsigned int g_ticket = 0;   // reset by last block -> graph-replayable

__device__ __forceinline__ float dot4(float4 a, float4 b) {
    return fmaf(a.x, b.x, fmaf(a.y, b.y, fmaf(a.z, b.z, a.w * b.w)));
}

__device__ __forceinline__ void butterfly10(float v[10]) {
    #pragma unroll
    for (int off = 16; off > 0; off >>= 1) {
        #pragma unroll
        for (int k = 0; k < 10; k++)
            v[k] += __shfl_xor_sync(0xFFFFFFFFu, v[k], off);
    }
}

// Lanes 0..3 each evaluate one anchor's weighted 3-way log-softmax; others 0.
__device__ __forceinline__ float softmax_acc(const float v[10], int lane,
                                             const float* __restrict__ sl) {
    if (lane >= 4) return 0.0f;

    float r0 = rsqrtf(fmaxf(v[0], 1e-16f));
    float r1 = rsqrtf(fmaxf(v[1], 1e-16f));
    float r2 = rsqrtf(fmaxf(v[2], 1e-16f));
    float r3 = rsqrtf(fmaxf(v[3], 1e-16f));

    float s01 = v[4] * (r0 * r1);
    float s02 = v[5] * (r0 * r2);
    float s03 = v[6] * (r0 * r3);
    float s12 = v[7] * (r1 * r2);
    float s13 = v[8] * (r1 * r3);
    float s23 = v[9] * (r2 * r3);

    // anchor i logits (pos, neg0, neg1):
    // i=0:(s02,s01,s03) i=1:(s13,s01,s12) i=2:(s02,s12,s23) i=3:(s13,s03,s23)
    float p  = (lane & 1)  ? s13 : s02;
    float n0 = (lane < 2)  ? s01 : ((lane == 2) ? s12 : s03);
    float n1 = (lane == 0) ? s03 : ((lane == 1) ? s12 : s23);

    const float invT = 2.0f;  // 1/TEMPERATURE, T = 0.5
    float l0 = p * invT, l1 = n0 * invT, l2 = n1 * invT;

    float m   = fmaxf(l0, fmaxf(l1, l2));
    float e   = __expf(l0 - m) + __expf(l1 - m) + __expf(l2 - m);
    float lse = m + __logf(e);

    float w0 = __ldg(sl + lane * 3 + 0);
    float w1 = __ldg(sl + lane * 3 + 1);
    float w2 = __ldg(sl + lane * 3 + 2);

    return (lse - l0) * w0 + (lse - l1) * w1 + (lse - l2) * w2;
}

__global__ __launch_bounds__(NTHREADS, 5)
void ntxent_kernel(const float* __restrict__ zis,
                   const float* __restrict__ zjs,
                   const float* __restrict__ soft_labels,
                   float* __restrict__ out,
                   int nc)
{
    __shared__ float wsum[NWARPS];
    __shared__ bool  is_last;

    const int tid  = threadIdx.x;
    const int warp = tid >> 5;
    const int lane = tid & 31;

    // Persistent: each warp owns a CONTIGUOUS chunk of groups (DRAM-page friendly).
    const int W   = GRID * NWARPS;                 // 5920 warps
    const int wid = blockIdx.x * NWARPS + warp;
    const int q   = nc / W;
    const int rem = nc - q * W;
    const int start = wid * q + (wid < rem ? wid : rem);
    const int cnt   = q + (wid < rem ? 1 : 0);

    const float4* zj4 = reinterpret_cast<const float4*>(zjs);
    const float4* zi4 = reinterpret_cast<const float4*>(zis);

    float acc = 0.0f;

    for (int k = 0; k < cnt; k++) {
        const int g = start + k;
        const float4* pj = zj4 + (size_t)g * (2 * F4_PER_ROW);
        const float4* pi = zi4 + (size_t)g * (2 * F4_PER_ROW);

        // Front-batched: 8 independent LDG.128 per lane
        float4 a0 = pj[lane];       float4 a1 = pj[lane + 32];
        float4 b0 = pj[lane + 64];  float4 b1 = pj[lane + 96];
        float4 c0 = pi[lane];       float4 c1 = pi[lane + 32];
        float4 d0 = pi[lane + 64];  float4 d1 = pi[lane + 96];

        float v[10];
        v[0] = dot4(a0, a0) + dot4(a1, a1);
        v[1] = dot4(b0, b0) + dot4(b1, b1);
        v[2] = dot4(c0, c0) + dot4(c1, c1);
        v[3] = dot4(d0, d0) + dot4(d1, d1);
        v[4] = dot4(a0, b0) + dot4(a1, b1);
        v[5] = dot4(a0, c0) + dot4(a1, c1);
        v[6] = dot4(a0, d0) + dot4(a1, d1);
        v[7] = dot4(b0, c0) + dot4(b1, c1);
        v[8] = dot4(b0, d0) + dot4(b1, d1);
        v[9] = dot4(c0, d0) + dot4(c1, d1);

        butterfly10(v);
        acc += softmax_acc(v, lane, soft_labels);
    }

    // fold lanes 0..3 -> lane 0
    acc += __shfl_xor_sync(0xFFFFFFFFu, acc, 1);
    acc += __shfl_xor_sync(0xFFFFFFFFu, acc, 2);
    if (lane == 0) wsum[warp] = acc;
    __syncthreads();

    if (tid == 0) {
        float t = 0.0f;
        #pragma unroll
        for (int w = 0; w < NWARPS; w++) t += wsum[w];
        g_partials[blockIdx.x] = t;
        __threadfence();
        unsigned old = atomicAdd(&g_ticket, 1u);
        is_last = (old == (unsigned)(gridDim.x - 1));
    }
    __syncthreads();

    if (is_last) {
        __threadfence();
        float t = 0.0f;
        for (int i = tid; i < (int)gridDim.x; i += NTHREADS)
            t += g_partials[i];
        #pragma unroll
        for (int off = 16; off > 0; off >>= 1)
            t += __shfl_xor_sync(0xFFFFFFFFu, t, off);
        if (lane == 0) wsum[warp] = t;
        __syncthreads();
        if (tid == 0) {
            float tot = 0.0f;
            #pragma unroll
            for (int w = 0; w < NWARPS; w++) tot += wsum[w];
            out[0] = tot * (1.0f / (4.0f * (float)nc));  // 1/(2n)
            g_ticket = 0;   // reset for graph replay
        }
    }
}

extern "C" void kernel_launch(void* const* d_in, const int* in_sizes, int n_in,
                              void* d_out, int out_size)
{
    const float* zis = (const float*)d_in[0];
    const float* zjs = (const float*)d_in[1];
    const float* sl  = (const float*)d_in[2];
    float* out = (float*)d_out;

    int n  = in_sizes[0] / D;   // 65536 rows
    int nc = n / 2;             // 32768 groups

    ntxent_kernel<<<GRID, NTHREADS>>>(zis, zjs, sl, out, nc);
}

// round 10
// speedup vs baseline: 1.1911x; 1.0364x over previous
#include <cuda_runtime.h>

#define NWARPS 4
#define NTHREADS 128
#define D 256
#define F4_PER_ROW (D/4)
#define MAX_PART4 4096            // up to 16384 block partials

__device__ float4       g_part4[MAX_PART4];   // block partials, float4-packed
__device__ unsigned int g_ticket = 0;         // reset by last block (replayable)

__device__ __forceinline__ float dot4(float4 a, float4 b) {
    return fmaf(a.x, b.x, fmaf(a.y, b.y, fmaf(a.z, b.z, a.w * b.w)));
}

__device__ __forceinline__ float4 ldcs4(const float4* p) {
    return __ldcs(p);   // evict-first: data is single-use
}

__device__ __forceinline__ void butterfly10(float v[10]) {
    #pragma unroll
    for (int off = 16; off > 0; off >>= 1) {
        #pragma unroll
        for (int k = 0; k < 10; k++)
            v[k] += __shfl_xor_sync(0xFFFFFFFFu, v[k], off);
    }
}

// Lanes 0..3 each evaluate one anchor's weighted 3-way log-softmax; others 0.
__device__ __forceinline__ float softmax_acc(const float v[10], int lane,
                                             const float* __restrict__ sl) {
    if (lane >= 4) return 0.0f;

    float r0 = rsqrtf(fmaxf(v[0], 1e-16f));
    float r1 = rsqrtf(fmaxf(v[1], 1e-16f));
    float r2 = rsqrtf(fmaxf(v[2], 1e-16f));
    float r3 = rsqrtf(fmaxf(v[3], 1e-16f));

    float s01 = v[4] * (r0 * r1);
    float s02 = v[5] * (r0 * r2);
    float s03 = v[6] * (r0 * r3);
    float s12 = v[7] * (r1 * r2);
    float s13 = v[8] * (r1 * r3);
    float s23 = v[9] * (r2 * r3);

    // anchor i logits (pos, neg0, neg1):
    // i=0:(s02,s01,s03) i=1:(s13,s01,s12) i=2:(s02,s12,s23) i=3:(s13,s03,s23)
    float p  = (lane & 1)  ? s13 : s02;
    float n0 = (lane < 2)  ? s01 : ((lane == 2) ? s12 : s03);
    float n1 = (lane == 0) ? s03 : ((lane == 1) ? s12 : s23);

    const float invT = 2.0f;  // 1/TEMPERATURE, T = 0.5
    float l0 = p * invT, l1 = n0 * invT, l2 = n1 * invT;

    float m   = fmaxf(l0, fmaxf(l1, l2));
    float e   = __expf(l0 - m) + __expf(l1 - m) + __expf(l2 - m);
    float lse = m + __logf(e);

    float w0 = __ldg(sl + lane * 3 + 0);
    float w1 = __ldg(sl + lane * 3 + 1);
    float w2 = __ldg(sl + lane * 3 + 2);

    return (lse - l0) * w0 + (lse - l1) * w1 + (lse - l2) * w2;
}

__global__ __launch_bounds__(NTHREADS, 10)
void ntxent_kernel(const float* __restrict__ zis,
                   const float* __restrict__ zjs,
                   const float* __restrict__ soft_labels,
                   float* __restrict__ out,
                   int nc)
{
    __shared__ float wsum[NWARPS];
    __shared__ bool  is_last;

    const int tid  = threadIdx.x;
    const int warp = tid >> 5;
    const int lane = tid & 31;

    // One group per warp, one-shot CTA (HW CTA replacement = free pipelining).
    const int g = blockIdx.x * NWARPS + warp;

    float acc = 0.0f;
    if (g < nc) {
        const float4* pj = reinterpret_cast<const float4*>(zjs) + (size_t)g * (2 * F4_PER_ROW);
        const float4* pi = reinterpret_cast<const float4*>(zis) + (size_t)g * (2 * F4_PER_ROW);

        // Front-batched: 8 independent LDG.128 per lane (evict-first)
        float4 a0 = ldcs4(pj + lane);       float4 a1 = ldcs4(pj + lane + 32);
        float4 b0 = ldcs4(pj + lane + 64);  float4 b1 = ldcs4(pj + lane + 96);
        float4 c0 = ldcs4(pi + lane);       float4 c1 = ldcs4(pi + lane + 32);
        float4 d0 = ldcs4(pi + lane + 64);  float4 d1 = ldcs4(pi + lane + 96);

        float v[10];
        v[0] = dot4(a0, a0) + dot4(a1, a1);
        v[1] = dot4(b0, b0) + dot4(b1, b1);
        v[2] = dot4(c0, c0) + dot4(c1, c1);
        v[3] = dot4(d0, d0) + dot4(d1, d1);
        v[4] = dot4(a0, b0) + dot4(a1, b1);
        v[5] = dot4(a0, c0) + dot4(a1, c1);
        v[6] = dot4(a0, d0) + dot4(a1, d1);
        v[7] = dot4(b0, c0) + dot4(b1, c1);
        v[8] = dot4(b0, d0) + dot4(b1, d1);
        v[9] = dot4(c0, d0) + dot4(c1, d1);

        butterfly10(v);
        acc += softmax_acc(v, lane, soft_labels);
    }

    // fold lanes 0..3 -> lane 0
    acc += __shfl_xor_sync(0xFFFFFFFFu, acc, 1);
    acc += __shfl_xor_sync(0xFFFFFFFFu, acc, 2);
    if (lane == 0) wsum[warp] = acc;
    __syncthreads();

    // block partial -> scratch; last block finishes (no memset node)
    if (tid == 0) {
        float t = wsum[0] + wsum[1] + wsum[2] + wsum[3];
        reinterpret_cast<float*>(g_part4)[blockIdx.x] = t;
        __threadfence();
        unsigned old = atomicAdd(&g_ticket, 1u);
        is_last = (old == (unsigned)(gridDim.x - 1));
    }
    __syncthreads();

    if (is_last) {
        __threadfence();
        // Reduce gridDim.x partials, float4-packed (slots beyond grid are 0).
        const int n4 = (int)(gridDim.x + 3) >> 2;
        float t = 0.0f;
        for (int i = tid; i < n4; i += NTHREADS) {
            float4 p = g_part4[i];
            t += (p.x + p.y) + (p.z + p.w);
        }
        #pragma unroll
        for (int off = 16; off > 0; off >>= 1)
            t += __shfl_xor_sync(0xFFFFFFFFu, t, off);
        if (lane == 0) wsum[warp] = t;
        __syncthreads();
        if (tid == 0) {
            float tot = wsum[0] + wsum[1] + wsum[2] + wsum[3];
            out[0] = tot * (1.0f / (4.0f * (float)nc));  // 1/(2n)
            g_ticket = 0;   // reset for graph replay
        }
    }
}

extern "C" void kernel_launch(void* const* d_in, const int* in_sizes, int n_in,
                              void* d_out, int out_size)
{
    const float* zis = (const float*)d_in[0];
    const float* zjs = (const float*)d_in[1];
    const float* sl  = (const float*)d_in[2];
    float* out = (float*)d_out;

    int n  = in_sizes[0] / D;   // 65536 rows
    int nc = n / 2;             // 32768 groups

    int blocks = (nc + NWARPS - 1) / NWARPS;   // 8192
    ntxent_kernel<<<blocks, NTHREADS>>>(zis, zjs, sl, out, nc);
}